// round 1
// baseline (speedup 1.0000x reference)
#include <cuda_runtime.h>

// RNN: B=512, T=512, D=64, H=512, O=1
//   xw = x @ W_x + b_rnn                        [B,T,H]
//   h_t = relu(xw_t + h_{t-1} @ W_h)            (h_0 = 0)
//   out = relu(h_T @ W_d + b_d)                 [B,1]
//
// Strategy: batch rows are independent across the whole recurrence.
// 128 CTAs x 128 threads, 4 batch rows per CTA, single launch, no
// inter-CTA sync. h kept transposed in SMEM as float4 (4 rows packed).
// W_x cached in SMEM (128KB); W_h streamed from L2 (1MB, L2-resident).

#define BSZ 512
#define TSZ 512
#define DSZ 64
#define HSZ 512
#define ROWS 4
#define NTHR 128
#define NCTA (BSZ / ROWS)   // 128

// dynamic smem layout (floats):
//  wx_s   : 64*512        = 32768 f  (131072 B)
//  hs4    : 512 float4    =  2048 f  (  8192 B)
//  xs4    : 64  float4    =   256 f  (  1024 B)
//  wd_s   : 512           =   512 f  (  2048 B)
//  br_s   : 512           =   512 f  (  2048 B)
//  part   : 128 float4    =   512 f  (  2048 B)
#define SMEM_BYTES (131072 + 8192 + 1024 + 2048 + 2048 + 2048)

__device__ __forceinline__ float4 fma4s(float a, float4 v, float4 acc) {
    acc.x = fmaf(a, v.x, acc.x);
    acc.y = fmaf(a, v.y, acc.y);
    acc.z = fmaf(a, v.z, acc.z);
    acc.w = fmaf(a, v.w, acc.w);
    return acc;
}

__device__ __forceinline__ float4 relu4(float4 v) {
    v.x = fmaxf(v.x, 0.f);
    v.y = fmaxf(v.y, 0.f);
    v.z = fmaxf(v.z, 0.f);
    v.w = fmaxf(v.w, 0.f);
    return v;
}

__global__ __launch_bounds__(NTHR, 1)
void rnn_persistent_kernel(const float* __restrict__ x,
                           const float* __restrict__ Wx,
                           const float* __restrict__ Wh,
                           const float* __restrict__ brnn,
                           const float* __restrict__ Wd,
                           const float* __restrict__ bd,
                           float* __restrict__ out)
{
    extern __shared__ float smem[];
    float*  wx_s = smem;                                   // [64][512]
    float4* hs4  = reinterpret_cast<float4*>(smem + DSZ * HSZ);      // [512]
    float4* xs4  = hs4 + HSZ;                              // [64]
    float*  wd_s = reinterpret_cast<float*>(xs4 + DSZ);    // [512]
    float*  br_s = wd_s + HSZ;                             // [512]
    float4* part = reinterpret_cast<float4*>(br_s + HSZ);  // [128]

    const int tid = threadIdx.x;
    const int b0  = blockIdx.x * ROWS;

    // ---- preload W_x, W_d, b_rnn into SMEM ----
    {
        const float4* wxg = reinterpret_cast<const float4*>(Wx);
        float4* wxs4 = reinterpret_cast<float4*>(wx_s);
        #pragma unroll 4
        for (int i = tid; i < DSZ * HSZ / 4; i += NTHR)
            wxs4[i] = wxg[i];
        for (int i = tid; i < HSZ; i += NTHR) {
            wd_s[i] = Wd[i];
            br_s[i] = brnn[i];
        }
    }
    __syncthreads();

    const float4* whq = reinterpret_cast<const float4*>(Wh) + tid;   // W_h[k][4t..4t+3]
    const float4* wxq = reinterpret_cast<const float4*>(wx_s) + tid;

    float4 acc0, acc1, acc2, acc3;   // acc[c] = column c of this thread, 4 rows

    for (int t = 0; t < TSZ; t++) {
        // ---- load x_t for our 4 rows, transposed into xs4[k] ----
        #pragma unroll
        for (int i = 0; i < 2; i++) {
            int idx = tid + i * NTHR;          // 0..255
            int r = idx >> 6;                  // 0..3
            int k = idx & 63;                  // 0..63
            reinterpret_cast<float*>(xs4)[k * 4 + r] =
                x[((size_t)(b0 + r) * TSZ + t) * DSZ + k];
        }
        __syncthreads();

        // ---- init accumulators with b_rnn ----
        float4 bias = reinterpret_cast<const float4*>(br_s)[tid];
        acc0 = make_float4(bias.x, bias.x, bias.x, bias.x);
        acc1 = make_float4(bias.y, bias.y, bias.y, bias.y);
        acc2 = make_float4(bias.z, bias.z, bias.z, bias.z);
        acc3 = make_float4(bias.w, bias.w, bias.w, bias.w);

        // ---- input projection: acc += x_t @ W_x  (K = 64, SMEM-resident) ----
        #pragma unroll 8
        for (int k = 0; k < DSZ; k++) {
            float4 w  = wxq[k * (HSZ / 4)];
            float4 xv = xs4[k];
            acc0 = fma4s(w.x, xv, acc0);
            acc1 = fma4s(w.y, xv, acc1);
            acc2 = fma4s(w.z, xv, acc2);
            acc3 = fma4s(w.w, xv, acc3);
        }

        // ---- recurrence: acc += h_{t-1} @ W_h  (K = 512, W_h from L2) ----
        if (t > 0) {
            #pragma unroll 8
            for (int k = 0; k < HSZ; k++) {
                float4 w  = whq[k * (HSZ / 4)];
                float4 hv = hs4[k];
                acc0 = fma4s(w.x, hv, acc0);
                acc1 = fma4s(w.y, hv, acc1);
                acc2 = fma4s(w.z, hv, acc2);
                acc3 = fma4s(w.w, hv, acc3);
            }
        }

        __syncthreads();   // all hs4 reads complete before overwrite

        acc0 = relu4(acc0);
        acc1 = relu4(acc1);
        acc2 = relu4(acc2);
        acc3 = relu4(acc3);

        hs4[4 * tid + 0] = acc0;
        hs4[4 * tid + 1] = acc1;
        hs4[4 * tid + 2] = acc2;
        hs4[4 * tid + 3] = acc3;
        __syncthreads();   // h_t visible to all warps for step t+1
    }

    // ---- final dense: out[b] = relu(h_T[b,:] @ W_d + b_d) ----
    // acc[c] still holds relu'd final h for columns 4*tid+c, rows 0..3.
    {
        float4 p = make_float4(0.f, 0.f, 0.f, 0.f);
        float w0 = wd_s[4 * tid + 0];
        float w1 = wd_s[4 * tid + 1];
        float w2 = wd_s[4 * tid + 2];
        float w3 = wd_s[4 * tid + 3];
        p = fma4s(w0, acc0, p);
        p = fma4s(w1, acc1, p);
        p = fma4s(w2, acc2, p);
        p = fma4s(w3, acc3, p);
        part[tid] = p;
    }
    __syncthreads();

    if (tid < ROWS) {
        float s = 0.f;
        const float* pf = reinterpret_cast<const float*>(part);
        for (int i = 0; i < NTHR; i++)
            s += pf[i * 4 + tid];
        out[b0 + tid] = fmaxf(s + bd[0], 0.f);
    }
}

extern "C" void kernel_launch(void* const* d_in, const int* in_sizes, int n_in,
                              void* d_out, int out_size) {
    const float* x    = (const float*)d_in[0];
    const float* Wx   = (const float*)d_in[1];
    const float* Wh   = (const float*)d_in[2];
    const float* brnn = (const float*)d_in[3];
    const float* Wd   = (const float*)d_in[4];
    const float* bd   = (const float*)d_in[5];
    float* out = (float*)d_out;

    cudaFuncSetAttribute(rnn_persistent_kernel,
                         cudaFuncAttributeMaxDynamicSharedMemorySize, SMEM_BYTES);

    rnn_persistent_kernel<<<NCTA, NTHR, SMEM_BYTES>>>(x, Wx, Wh, brnn, Wd, bd, out);
}

// round 3
// speedup vs baseline: 1.5992x; 1.5992x over previous
#include <cuda_runtime.h>

// RNN: B=512, T=512, D=64, H=512, O=1
//   h_t = relu(x_t @ W_x + b + h_{t-1} @ W_h),  out = relu(h_T @ W_d + b_d)
//
// R2: 128 CTAs x 256 threads (2 warps/SMSP). Each CTA owns 4 batch rows;
// each thread owns 2 columns x 4 rows (8 fp32 accumulators).
// h transposed in SMEM as float4 (4 rows packed). W_x (128KB) + first
// KC=40 rows of W_h (80KB) cached in SMEM; rest of W_h streamed from L2.

#define BSZ 512
#define TSZ 512
#define DSZ 64
#define HSZ 512
#define ROWS 4
#define NTHR 256
#define NCTA (BSZ / ROWS)   // 128
#define KC   40             // W_h rows cached in SMEM

// smem (floats): wx 32768 | whc KC*512 | hs4 2048 | xs4 256 | wd 512 | br 512 | part 1024
#define SMEM_FLOATS (32768 + KC*512 + 2048 + 256 + 512 + 512 + 1024)
#define SMEM_BYTES  (SMEM_FLOATS * 4)   // 230400 <= 232448

__device__ __forceinline__ float4 fma4s(float a, float4 v, float4 acc) {
    acc.x = fmaf(a, v.x, acc.x);
    acc.y = fmaf(a, v.y, acc.y);
    acc.z = fmaf(a, v.z, acc.z);
    acc.w = fmaf(a, v.w, acc.w);
    return acc;
}

__device__ __forceinline__ float4 relu4(float4 v) {
    v.x = fmaxf(v.x, 0.f);
    v.y = fmaxf(v.y, 0.f);
    v.z = fmaxf(v.z, 0.f);
    v.w = fmaxf(v.w, 0.f);
    return v;
}

__global__ __launch_bounds__(NTHR, 1)
void rnn_persistent_kernel(const float* __restrict__ x,
                           const float* __restrict__ Wx,
                           const float* __restrict__ Wh,
                           const float* __restrict__ brnn,
                           const float* __restrict__ Wd,
                           const float* __restrict__ bd,
                           float* __restrict__ out)
{
    extern __shared__ float smem[];
    float*  wx_s = smem;                                        // [64][512]
    float*  whc  = wx_s + DSZ * HSZ;                            // [KC][512]
    float4* hs4  = reinterpret_cast<float4*>(whc + KC * HSZ);   // [512]
    float4* xs4  = hs4 + HSZ;                                   // [64]
    float*  wd_s = reinterpret_cast<float*>(xs4 + DSZ);         // [512]
    float*  br_s = wd_s + HSZ;                                  // [512]
    float4* part = reinterpret_cast<float4*>(br_s + HSZ);       // [256]

    const int tid = threadIdx.x;
    const int b0  = blockIdx.x * ROWS;

    // ---- preload W_x, W_h[0:KC], W_d, b_rnn ----
    {
        const float4* wxg = reinterpret_cast<const float4*>(Wx);
        float4* d = reinterpret_cast<float4*>(wx_s);
        #pragma unroll 4
        for (int i = tid; i < DSZ * HSZ / 4; i += NTHR) d[i] = wxg[i];
        const float4* whg = reinterpret_cast<const float4*>(Wh);
        float4* wc = reinterpret_cast<float4*>(whc);
        #pragma unroll 4
        for (int i = tid; i < KC * HSZ / 4; i += NTHR) wc[i] = whg[i];
        for (int i = tid; i < HSZ; i += NTHR) {
            wd_s[i] = Wd[i];
            br_s[i] = brnn[i];
        }
    }
    __syncthreads();

    // per-thread column pair: c0 = 2*tid, c1 = 2*tid+1
    const float2* wxp = reinterpret_cast<const float2*>(wx_s) + tid;  // [k*256]
    const float2* wcp = reinterpret_cast<const float2*>(whc) + tid;
    const float2* whp = reinterpret_cast<const float2*>(Wh) + tid;

    float4 accA, accB;   // rows 0..3 for col c0 (A) and c1 (B)

    for (int t = 0; t < TSZ; t++) {
        // ---- stage x_t transposed into xs4[k] (256 elems, one per thread) ----
        {
            int r = tid >> 6;       // 0..3
            int k = tid & 63;       // 0..63
            reinterpret_cast<float*>(xs4)[k * 4 + r] =
                x[((size_t)(b0 + r) * TSZ + t) * DSZ + k];
        }
        __syncthreads();

        // ---- init with bias ----
        {
            float2 bb = reinterpret_cast<const float2*>(br_s)[tid];
            accA = make_float4(bb.x, bb.x, bb.x, bb.x);
            accB = make_float4(bb.y, bb.y, bb.y, bb.y);
        }

        // ---- input projection (K=64, all SMEM) ----
        #pragma unroll 8
        for (int k = 0; k < DSZ; k++) {
            float2 w  = wxp[k * (HSZ / 2)];
            float4 xv = xs4[k];
            accA = fma4s(w.x, xv, accA);
            accB = fma4s(w.y, xv, accB);
        }

        // ---- recurrence (K=512) ----
        if (t > 0) {
            #pragma unroll 8
            for (int k = 0; k < KC; k++) {            // SMEM-cached rows
                float2 w  = wcp[k * (HSZ / 2)];
                float4 hv = hs4[k];
                accA = fma4s(w.x, hv, accA);
                accB = fma4s(w.y, hv, accB);
            }
            #pragma unroll 8
            for (int k = KC; k < HSZ; k++) {          // L2-streamed rows
                float2 w  = whp[k * (HSZ / 2)];
                float4 hv = hs4[k];
                accA = fma4s(w.x, hv, accA);
                accB = fma4s(w.y, hv, accB);
            }
        }

        __syncthreads();   // all hs4 reads done before overwrite

        accA = relu4(accA);
        accB = relu4(accB);
        hs4[2 * tid + 0] = accA;
        hs4[2 * tid + 1] = accB;
        __syncthreads();   // h_t visible to all warps
    }

    // ---- final dense: out[b] = relu(h_T[b,:] @ W_d + b_d) ----
    {
        float w0 = wd_s[2 * tid + 0];
        float w1 = wd_s[2 * tid + 1];
        float4 p = make_float4(0.f, 0.f, 0.f, 0.f);
        p = fma4s(w0, accA, p);
        p = fma4s(w1, accB, p);
        part[tid] = p;
    }
    __syncthreads();

    if (tid < ROWS) {
        float s = 0.f;
        const float* pf = reinterpret_cast<const float*>(part);
        #pragma unroll 8
        for (int i = 0; i < NTHR; i++)
            s += pf[i * 4 + tid];
        out[b0 + tid] = fmaxf(s + bd[0], 0.f);
    }
}

extern "C" void kernel_launch(void* const* d_in, const int* in_sizes, int n_in,
                              void* d_out, int out_size) {
    const float* x    = (const float*)d_in[0];
    const float* Wx   = (const float*)d_in[1];
    const float* Wh   = (const float*)d_in[2];
    const float* brnn = (const float*)d_in[3];
    const float* Wd   = (const float*)d_in[4];
    const float* bd   = (const float*)d_in[5];
    float* out = (float*)d_out;

    cudaFuncSetAttribute(rnn_persistent_kernel,
                         cudaFuncAttributeMaxDynamicSharedMemorySize, SMEM_BYTES);

    rnn_persistent_kernel<<<NCTA, NTHR, SMEM_BYTES>>>(x, Wx, Wh, brnn, Wd, bd, out);
}